// round 16
// baseline (speedup 1.0000x reference)
#include <cuda_runtime.h>
#include <cuda_fp16.h>

#define DIMC 512
#define NH   8
#define HD   64
#define BATCH 4
#define NQ   1024
#define NKV  1024
#define TABLE 66049   // 257*257
#define LOG2E 1.44269504f

// ---------------- scratch (device globals: no allocation allowed) ----------
__device__ unsigned g_q [BATCH*NH*NQ *32];   // fp16 half2 words [B][H][N][32]; Q pre-scaled by 0.125*log2e
__device__ unsigned g_k [BATCH*NH*NKV*32];
__device__ unsigned g_v [BATCH*NH*NKV*32];
__device__ float    g_xo[BATCH*NQ*DIMC];
__device__ float    g_lam[NH/2];
__device__ unsigned g_rpk[TABLE*4];          // half2(rpe[idx][p], rpe[idx][p+4]) * log2e

// ---------------- lambda ---------------------------------------------------
__global__ void lam_kernel(const float* __restrict__ lq1, const float* __restrict__ lk1,
                           const float* __restrict__ lq2, const float* __restrict__ lk2)
{
    int p = threadIdx.x;
    if (p < NH/2) {
        float a = 0.f, c = 0.f;
        for (int d = 0; d < HD; d++) {
            a += lq1[p*HD+d] * lk1[p*HD+d];
            c += lq2[p*HD+d] * lk2[p*HD+d];
        }
        g_lam[p] = __expf(a) - __expf(c) + 0.8f;
    }
}

// ---------------- RPE repack: half2(h, h+4)*log2e per (idx, pair) ----------
__global__ void rpk_kernel(const float* __restrict__ rpe)
{
    int i = blockIdx.x*256 + threadIdx.x;
    if (i < TABLE*4) {
        int idx = i >> 2, p = i & 3;
        __half2 h = __floats2half2_rn(rpe[idx*8 + p]*LOG2E, rpe[idx*8 + p + 4]*LOG2E);
        g_rpk[i] = *(unsigned*)&h;
    }
}

// ---------------- helpers ---------------------------------------------------
__device__ __forceinline__ void mma_f16(float c[4],
    unsigned a0, unsigned a1, unsigned a2, unsigned a3,
    unsigned b0, unsigned b1)
{
    asm volatile(
        "mma.sync.aligned.m16n8k16.row.col.f32.f16.f16.f32 "
        "{%0,%1,%2,%3},{%4,%5,%6,%7},{%8,%9},{%0,%1,%2,%3};\n"
        : "+f"(c[0]), "+f"(c[1]), "+f"(c[2]), "+f"(c[3])
        : "r"(a0), "r"(a1), "r"(a2), "r"(a3), "r"(b0), "r"(b1));
}

__device__ __forceinline__ void ldsm_x4(
    unsigned& r0, unsigned& r1, unsigned& r2, unsigned& r3, unsigned saddr)
{
    asm volatile(
        "ldmatrix.sync.aligned.m8n8.x4.shared.b16 {%0,%1,%2,%3}, [%4];"
        : "=r"(r0), "=r"(r1), "=r"(r2), "=r"(r3) : "r"(saddr));
}

__device__ __forceinline__ void ldsm_x4_trans(
    unsigned& r0, unsigned& r1, unsigned& r2, unsigned& r3, unsigned saddr)
{
    asm volatile(
        "ldmatrix.sync.aligned.m8n8.x4.trans.shared.b16 {%0,%1,%2,%3}, [%4];"
        : "=r"(r0), "=r"(r1), "=r"(r2), "=r"(r3) : "r"(saddr));
}

__device__ __forceinline__ unsigned pack_h2(float lo, float hi) {
    __half2 h = __floats2half2_rn(lo, hi);
    return *(unsigned*)&h;
}
__device__ __forceinline__ unsigned h2u(__half2 h) { return *(unsigned*)&h; }
__device__ __forceinline__ float ex2(float x) {
    float r; asm("ex2.approx.f32 %0, %1;" : "=f"(r) : "f"(x)); return r;
}

// ---------------- fp16 GEMM (R14 winner + output-scale param) --------------
#define GST 20

__device__ __forceinline__ void gemm_body(
    const float* __restrict__ A, const float* __restrict__ W,
    const float* __restrict__ bias, void* __restrict__ C,
    int mode, int bm, int bn, float osc)
{
    __shared__ unsigned As[2][128][GST];
    __shared__ unsigned Ws[2][64][GST];

    int tid  = threadIdx.x;
    int wid  = tid >> 5;
    int lane = tid & 31;
    int g    = lane >> 2;
    int tg   = lane & 3;
    int wm   = (wid >> 1) * 32;
    int wn   = (wid & 1) * 32;

    float acc[2][4][4];
#pragma unroll
    for (int mf = 0; mf < 2; mf++)
#pragma unroll
        for (int nf = 0; nf < 4; nf++)
#pragma unroll
            for (int e = 0; e < 4; e++) acc[mf][nf][e] = 0.f;

    int rA = tid >> 1, hA = tid & 1;
    const float* Arow = A + (size_t)(bm + rA) * DIMC + hA * 16;
    int rW = tid >> 2, qW = tid & 3;
    const float* Wrow = W + (size_t)(bn + rW) * DIMC + qW * 8;

    float4 av[4], wv[2];
#pragma unroll
    for (int i = 0; i < 4; i++) av[i] = *(const float4*)(Arow + 4*i);
    wv[0] = *(const float4*)(Wrow);
    wv[1] = *(const float4*)(Wrow + 4);

#pragma unroll
    for (int i = 0; i < 4; i++) {
        As[0][rA][hA*8 + 2*i]   = pack_h2(av[i].x, av[i].y);
        As[0][rA][hA*8 + 2*i+1] = pack_h2(av[i].z, av[i].w);
    }
    Ws[0][rW][qW*4+0] = pack_h2(wv[0].x, wv[0].y);
    Ws[0][rW][qW*4+1] = pack_h2(wv[0].z, wv[0].w);
    Ws[0][rW][qW*4+2] = pack_h2(wv[1].x, wv[1].y);
    Ws[0][rW][qW*4+3] = pack_h2(wv[1].z, wv[1].w);
    __syncthreads();

    for (int k0 = 0; k0 < DIMC; k0 += 32) {
        int  buf  = (k0 >> 5) & 1;
        bool more = (k0 + 32 < DIMC);
        if (more) {
#pragma unroll
            for (int i = 0; i < 4; i++)
                av[i] = *(const float4*)(Arow + k0 + 32 + 4*i);
            wv[0] = *(const float4*)(Wrow + k0 + 32);
            wv[1] = *(const float4*)(Wrow + k0 + 36);
        }

#pragma unroll
        for (int s = 0; s < 2; s++) {
            int kw = s * 8;
            unsigned af[2][4], bf[4][2];
#pragma unroll
            for (int mf = 0; mf < 2; mf++) {
                int m0 = wm + mf*16 + g;
                af[mf][0] = As[buf][m0  ][kw+tg];
                af[mf][1] = As[buf][m0+8][kw+tg];
                af[mf][2] = As[buf][m0  ][kw+4+tg];
                af[mf][3] = As[buf][m0+8][kw+4+tg];
            }
#pragma unroll
            for (int nf = 0; nf < 4; nf++) {
                int n0 = wn + nf*8 + g;
                bf[nf][0] = Ws[buf][n0][kw+tg];
                bf[nf][1] = Ws[buf][n0][kw+4+tg];
            }
#pragma unroll
            for (int mf = 0; mf < 2; mf++)
#pragma unroll
                for (int nf = 0; nf < 4; nf++)
                    mma_f16(acc[mf][nf], af[mf][0], af[mf][1], af[mf][2], af[mf][3],
                            bf[nf][0], bf[nf][1]);
        }

        if (more) {
            int nb = buf ^ 1;
#pragma unroll
            for (int i = 0; i < 4; i++) {
                As[nb][rA][hA*8 + 2*i]   = pack_h2(av[i].x, av[i].y);
                As[nb][rA][hA*8 + 2*i+1] = pack_h2(av[i].z, av[i].w);
            }
            Ws[nb][rW][qW*4+0] = pack_h2(wv[0].x, wv[0].y);
            Ws[nb][rW][qW*4+1] = pack_h2(wv[0].z, wv[0].w);
            Ws[nb][rW][qW*4+2] = pack_h2(wv[1].x, wv[1].y);
            Ws[nb][rW][qW*4+3] = pack_h2(wv[1].z, wv[1].w);
            __syncthreads();
        }
    }

#pragma unroll
    for (int nf = 0; nf < 4; nf++) {
        int c0 = bn + wn + nf*8 + 2*tg;
        float b0 = bias[c0], b1 = bias[c0+1];
#pragma unroll
        for (int mf = 0; mf < 2; mf++) {
            int r0 = bm + wm + mf*16 + g;
            float2 o0 = {acc[mf][nf][0] + b0, acc[mf][nf][1] + b1};
            float2 o1 = {acc[mf][nf][2] + b0, acc[mf][nf][3] + b1};
            if (mode == 0) {
                *(float2*)((float*)C + (size_t)r0*DIMC + c0)     = o0;
                *(float2*)((float*)C + (size_t)(r0+8)*DIMC + c0) = o1;
            } else {
                unsigned w0 = pack_h2(o0.x*osc, o0.y*osc);
                unsigned w1 = pack_h2(o1.x*osc, o1.y*osc);
                int h = c0 >> 6, hp = (c0 & 63) >> 1;
                int b_  = r0 >> 10, nq = r0 & 1023;
                ((unsigned*)C)[((size_t)(b_*NH + h)*NQ + nq)*32 + hp] = w0;
                b_ = (r0+8) >> 10; nq = (r0+8) & 1023;
                ((unsigned*)C)[((size_t)(b_*NH + h)*NQ + nq)*32 + hp] = w1;
            }
        }
    }
}

__global__ __launch_bounds__(256) void qkv_kernel(
    const float* __restrict__ x_q, const float* __restrict__ x_kv,
    const float* __restrict__ Wq, const float* __restrict__ bq,
    const float* __restrict__ Wk, const float* __restrict__ bk,
    const float* __restrict__ Wv, const float* __restrict__ bv)
{
    int z = blockIdx.z;
    const float* A    = (z == 0) ? x_q : x_kv;
    const float* W    = (z == 0) ? Wq : (z == 1) ? Wk : Wv;
    const float* bias = (z == 0) ? bq : (z == 1) ? bk : bv;
    void* C           = (z == 0) ? (void*)g_q : (z == 1) ? (void*)g_k : (void*)g_v;
    float osc         = (z == 0) ? 0.125f*LOG2E : 1.f;
    gemm_body(A, W, bias, C, 1, blockIdx.x*128, blockIdx.y*64, osc);
}

__global__ __launch_bounds__(256) void proj_kernel(
    const float* __restrict__ Wp, const float* __restrict__ bp, float* __restrict__ out)
{
    gemm_body(g_xo, Wp, bp, out, 0, blockIdx.x*128, blockIdx.y*64, 1.f);
}

// ---------------- fp16 tensor-core differential flash attention -------------
// R15 structure with:
//  - double-buffered bias tiles, gathered ONE TILE AHEAD (L2 latency hidden
//    under a full tile of compute); barrier count 4 -> 3 per tile
//  - score accumulators INITIALIZED from bias (log2e-folded); Q pre-scaled
//    by 0.125*log2e in the GEMM -> softmax uses bare ex2, no scale/add block
#define ST 36
#define TW (64*ST)

__global__ __launch_bounds__(256, 2) void attn_kernel(
    const int* __restrict__ coords_q, const int* __restrict__ coords_k,
    const float* __restrict__ alpha_map)
{
    extern __shared__ __align__(16) unsigned su[];
    unsigned* sQ1 = su;            // [64][36] half2 words
    unsigned* sQ2 = sQ1 + TW;
    unsigned* sK1 = sQ2 + TW;
    unsigned* sK2 = sK1 + TW;
    unsigned* sV1 = sK2 + TW;
    unsigned* sV2 = sV1 + TW;
    unsigned* sS1 = sV2 + TW;      // P tiles (fp16 pairs)
    unsigned* sS2 = sS1 + TW;
    unsigned* sB1 = sS2 + TW;      // bias tiles [2][TW] (fp16 pairs, log2e units)
    unsigned* sB2 = sB1 + 2*TW;
    float* sC1 = (float*)(sB2 + 2*TW); // [64] corrections
    float* sC2 = sC1 + 64;
    float* sL1 = sC2 + 64;             // [64] final l
    float* sL2 = sL1 + 64;

    int tid  = threadIdx.x;
    int w    = tid >> 5;
    int lane = tid & 31;
    int g    = lane >> 2;
    int tg   = lane & 3;

    int qb = blockIdx.x * 64;
    int p  = blockIdx.y;
    int b  = blockIdx.z;
    int h1 = p, h2 = p + 4;

    int sh  = w >> 2;          // score head
    int sm0 = (w & 3) * 16;    // score m-strip
    int pm0 = (w >> 1) * 16;   // PV m-strip
    int pn0 = (w & 1) * 32;    // PV n-half

    const unsigned* q1g = g_q + ((size_t)(b*NH+h1)*NQ + qb)*32;
    const unsigned* q2g = g_q + ((size_t)(b*NH+h2)*NQ + qb)*32;
    const unsigned* k1base = g_k + ((size_t)(b*NH+h1)*NKV)*32;
    const unsigned* k2base = g_k + ((size_t)(b*NH+h2)*NKV)*32;
    const unsigned* v1base = g_v + ((size_t)(b*NH+h1)*NKV)*32;
    const unsigned* v2base = g_v + ((size_t)(b*NH+h2)*NKV)*32;
    const int* ckbase = coords_k + (size_t)b*NKV*2;

    // ---- stage Q ----
    for (int c = tid; c < 512; c += 256) {
        int row = c >> 3, seg = (c & 7) * 4;
        *(uint4*)&sQ1[row*ST+seg] = *(const uint4*)(q1g + row*32 + seg);
        *(uint4*)&sQ2[row*ST+seg] = *(const uint4*)(q2g + row*32 + seg);
    }

    int sr0 = sm0 + g, sr1 = sm0 + g + 8;
    int cqx0 = 0, cqy0 = 0, cqx1 = 0, cqy1 = 0;
    if (sh == 0) {
        cqx0 = coords_q[((size_t)b*NQ + qb + sr0)*2];
        cqy0 = coords_q[((size_t)b*NQ + qb + sr0)*2 + 1];
        cqx1 = coords_q[((size_t)b*NQ + qb + sr1)*2];
        cqy1 = coords_q[((size_t)b*NQ + qb + sr1)*2 + 1];
    }

    // ---- ldmatrix per-lane byte offsets ----
    int aRow = (lane & 7) + ((lane >> 3) & 1) * 8;
    unsigned aOff = (unsigned)((aRow*ST + (lane >> 4)*4) * 4);
    int kRow = ((lane >> 4) * 8) + (lane & 7);
    unsigned kOff = (unsigned)((kRow*ST + ((lane >> 3) & 1)*4) * 4);
    int lt = lane >> 3, lr = lane & 7;
    unsigned lmOff0 = ((((lt & 1) * 8 + lr) * ST) + (pn0 >> 1) + ((lt >> 1) * 4)) * 4;
    unsigned lmOff1 = lmOff0 + 32;

    unsigned sV1a = (unsigned)__cvta_generic_to_shared(sV1);
    unsigned sV2a = (unsigned)__cvta_generic_to_shared(sV2);
    unsigned sS1a = (unsigned)__cvta_generic_to_shared(sS1);
    unsigned sS2a = (unsigned)__cvta_generic_to_shared(sS2);

    float mOld0 = -1e30f, mOld1 = -1e30f, lRun0 = 0.f, lRun1 = 0.f;

    float pacc[3][4][4];
#pragma unroll
    for (int pr = 0; pr < 3; pr++)
#pragma unroll
        for (int nt = 0; nt < 4; nt++)
#pragma unroll
            for (int e = 0; e < 4; e++) pacc[pr][nt][e] = 0.f;

    const unsigned* Qs = sh ? sQ2 : sQ1;
    const unsigned* Ks = sh ? sK2 : sK1;
    unsigned* Ss       = sh ? sS2 : sS1;
    float* sCa         = sh ? sC2 : sC1;

    unsigned qFrag = (unsigned)__cvta_generic_to_shared(Qs) + (unsigned)(sm0*ST*4) + aOff;
    unsigned kFrag = (unsigned)__cvta_generic_to_shared(Ks) + kOff;
    unsigned p1Frag = sS1a + (unsigned)(pm0*ST*4) + aOff;
    unsigned p2Frag = sS2a + (unsigned)(pm0*ST*4) + aOff;

    // ---- prologue: gather bias for tile 0 into buffer 0 ----
    if (sh == 0) {
#pragma unroll
        for (int nt = 0; nt < 8; nt++) {
            int c0 = 8*nt + 2*tg;
            int4 cc = __ldg((const int4*)(ckbase + c0*2));
            int r0 = min(max(cqx0 - cc.x + 128, 0), 256);
            int r1 = min(max(cqy0 - cc.y + 128, 0), 256);
            unsigned w00 = __ldg(&g_rpk[(r0*257 + r1)*4 + p]);
            r0 = min(max(cqx0 - cc.z + 128, 0), 256);
            r1 = min(max(cqy0 - cc.w + 128, 0), 256);
            unsigned w01 = __ldg(&g_rpk[(r0*257 + r1)*4 + p]);
            __half2 a = *(__half2*)&w00, bb = *(__half2*)&w01;
            sB1[sr0*ST + 4*nt + tg] = h2u(__halves2half2(__low2half(a),  __low2half(bb)));
            sB2[sr0*ST + 4*nt + tg] = h2u(__halves2half2(__high2half(a), __high2half(bb)));
            r0 = min(max(cqx1 - cc.x + 128, 0), 256);
            r1 = min(max(cqy1 - cc.y + 128, 0), 256);
            unsigned w10 = __ldg(&g_rpk[(r0*257 + r1)*4 + p]);
            r0 = min(max(cqx1 - cc.z + 128, 0), 256);
            r1 = min(max(cqy1 - cc.w + 128, 0), 256);
            unsigned w11 = __ldg(&g_rpk[(r0*257 + r1)*4 + p]);
            __half2 c = *(__half2*)&w10, d = *(__half2*)&w11;
            sB1[sr1*ST + 4*nt + tg] = h2u(__halves2half2(__low2half(c),  __low2half(d)));
            sB2[sr1*ST + 4*nt + tg] = h2u(__halves2half2(__high2half(c), __high2half(d)));
        }
    }

    for (int t = 0; t < NKV/64; t++) {
        int kb = t * 64;
        int cur = t & 1, nxt = cur ^ 1;

        // ---- stage K/V ----
        for (int c = tid; c < 512; c += 256) {
            int row = c >> 3, seg = (c & 7) * 4;
            int go = (kb + row)*32 + seg;
            *(uint4*)&sK1[row*ST+seg] = *(const uint4*)(k1base + go);
            *(uint4*)&sK2[row*ST+seg] = *(const uint4*)(k2base + go);
            *(uint4*)&sV1[row*ST+seg] = *(const uint4*)(v1base + go);
            *(uint4*)&sV2[row*ST+seg] = *(const uint4*)(v2base + go);
        }
        __syncthreads();

        // ---- gather bias for tile t+1 into the other buffer (early issue) --
        if (sh == 0 && t + 1 < NKV/64) {
            const int* ck1 = ckbase + (kb + 64)*2;
            unsigned* B1n = sB1 + nxt*TW;
            unsigned* B2n = sB2 + nxt*TW;
#pragma unroll
            for (int nt = 0; nt < 8; nt++) {
                int c0 = 8*nt + 2*tg;
                int4 cc = __ldg((const int4*)(ck1 + c0*2));
                int r0 = min(max(cqx0 - cc.x + 128, 0), 256);
                int r1 = min(max(cqy0 - cc.y + 128, 0), 256);
                unsigned w00 = __ldg(&g_rpk[(r0*257 + r1)*4 + p]);
                r0 = min(max(cqx0 - cc.z + 128, 0), 256);
                r1 = min(max(cqy0 - cc.w + 128, 0), 256);
                unsigned w01 = __ldg(&g_rpk[(r0*257 + r1)*4 + p]);
                __half2 a = *(__half2*)&w00, bb = *(__half2*)&w01;
                B1n[sr0*ST + 4*nt + tg] = h2u(__halves2half2(__low2half(a),  __low2half(bb)));
                B2n[sr0*ST + 4*nt + tg] = h2u(__halves2half2(__high2half(a), __high2half(bb)));
                r0 = min(max(cqx1 - cc.x + 128, 0), 256);
                r1 = min(max(cqy1 - cc.y + 128, 0), 256);
                unsigned w10 = __ldg(&g_rpk[(r0*257 + r1)*4 + p]);
                r0 = min(max(cqx1 - cc.z + 128, 0), 256);
                r1 = min(max(cqy1 - cc.w + 128, 0), 256);
                unsigned w11 = __ldg(&g_rpk[(r0*257 + r1)*4 + p]);
                __half2 c = *(__half2*)&w10, d = *(__half2*)&w11;
                B1n[sr1*ST + 4*nt + tg] = h2u(__halves2half2(__low2half(c),  __low2half(d)));
                B2n[sr1*ST + 4*nt + tg] = h2u(__halves2half2(__high2half(c), __high2half(d)));
            }
        }

        // ---- init scores from bias (log2e units), then mma on top ----
        const unsigned* BsC = (sh ? sB2 : sB1) + cur*TW;
        float sc[8][4];
#pragma unroll
        for (int nt = 0; nt < 8; nt++) {
            __half2 b0 = *(__half2*)&BsC[sr0*ST + 4*nt + tg];
            __half2 b1 = *(__half2*)&BsC[sr1*ST + 4*nt + tg];
            sc[nt][0] = __low2float(b0);
            sc[nt][1] = __high2float(b0);
            sc[nt][2] = __low2float(b1);
            sc[nt][3] = __high2float(b1);
        }

#pragma unroll
        for (int s = 0; s < 4; s++) {
            unsigned a0, a1, a2, a3;
            ldsm_x4(a0, a1, a2, a3, qFrag + s*32);
#pragma unroll
            for (int np = 0; np < 4; np++) {
                unsigned b0, b1, c0, c1;
                ldsm_x4(b0, b1, c0, c1, kFrag + (unsigned)(np*16*ST*4) + s*32);
                mma_f16(sc[2*np],   a0, a1, a2, a3, b0, b1);
                mma_f16(sc[2*np+1], a0, a1, a2, a3, c0, c1);
            }
        }

        // ---- online softmax (log2 domain; rows sr0, sr1; quad reduction) ---
        float rm0 = sc[0][0], rm1 = sc[0][2];
#pragma unroll
        for (int nt = 0; nt < 8; nt++) {
            rm0 = fmaxf(rm0, fmaxf(sc[nt][0], sc[nt][1]));
            rm1 = fmaxf(rm1, fmaxf(sc[nt][2], sc[nt][3]));
        }
#pragma unroll
        for (int o = 1; o < 4; o <<= 1) {
            rm0 = fmaxf(rm0, __shfl_xor_sync(0xffffffffu, rm0, o));
            rm1 = fmaxf(rm1, __shfl_xor_sync(0xffffffffu, rm1, o));
        }
        float nm0 = fmaxf(mOld0, rm0), nm1 = fmaxf(mOld1, rm1);
        float corr0 = ex2(mOld0 - nm0), corr1 = ex2(mOld1 - nm1);

        float sum0 = 0.f, sum1 = 0.f;
#pragma unroll
        for (int nt = 0; nt < 8; nt++) {
            float e00 = ex2(sc[nt][0] - nm0);
            float e01 = ex2(sc[nt][1] - nm0);
            float e10 = ex2(sc[nt][2] - nm1);
            float e11 = ex2(sc[nt][3] - nm1);
            sum0 += e00 + e01;
            sum1 += e10 + e11;
            Ss[sr0*ST + 4*nt + tg] = pack_h2(e00, e01);
            Ss[sr1*ST + 4*nt + tg] = pack_h2(e10, e11);
        }
#pragma unroll
        for (int o = 1; o < 4; o <<= 1) {
            sum0 += __shfl_xor_sync(0xffffffffu, sum0, o);
            sum1 += __shfl_xor_sync(0xffffffffu, sum1, o);
        }
        lRun0 = lRun0*corr0 + sum0;
        lRun1 = lRun1*corr1 + sum1;
        mOld0 = nm0; mOld1 = nm1;
        if (tg == 0) { sCa[sr0] = corr0; sCa[sr1] = corr1; }
        __syncthreads();

        // ---- PV: rescale accumulators, then fp16 mma (ldmatrix P and V^T) --
        float c1r0 = sC1[pm0+g], c1r1 = sC1[pm0+g+8];
        float c2r0 = sC2[pm0+g], c2r1 = sC2[pm0+g+8];
#pragma unroll
        for (int nt = 0; nt < 4; nt++) {
            pacc[0][nt][0] *= c1r0; pacc[0][nt][1] *= c1r0;
            pacc[0][nt][2] *= c1r1; pacc[0][nt][3] *= c1r1;
            pacc[1][nt][0] *= c2r0; pacc[1][nt][1] *= c2r0;
            pacc[1][nt][2] *= c2r1; pacc[1][nt][3] *= c2r1;
            pacc[2][nt][0] *= c2r0; pacc[2][nt][1] *= c2r0;
            pacc[2][nt][2] *= c2r1; pacc[2][nt][3] *= c2r1;
        }

#pragma unroll
        for (int s = 0; s < 4; s++) {
            unsigned p1a0, p1a1, p1a2, p1a3, p2a0, p2a1, p2a2, p2a3;
            ldsm_x4(p1a0, p1a1, p1a2, p1a3, p1Frag + s*32);
            ldsm_x4(p2a0, p2a1, p2a2, p2a3, p2Frag + s*32);

            unsigned rowB = (unsigned)(s * 16 * ST * 4);
            unsigned va[8], vb[8];
            ldsm_x4_trans(va[0], va[1], va[2], va[3], sV1a + rowB + lmOff0);
            ldsm_x4_trans(va[4], va[5], va[6], va[7], sV1a + rowB + lmOff1);
            ldsm_x4_trans(vb[0], vb[1], vb[2], vb[3], sV2a + rowB + lmOff0);
            ldsm_x4_trans(vb[4], vb[5], vb[6], vb[7], sV2a + rowB + lmOff1);

#pragma unroll
            for (int nt = 0; nt < 4; nt++) {
                mma_f16(pacc[0][nt], p1a0, p1a1, p1a2, p1a3, va[2*nt], va[2*nt+1]);
                mma_f16(pacc[1][nt], p2a0, p2a1, p2a2, p2a3, va[2*nt], va[2*nt+1]);
                mma_f16(pacc[2][nt], p2a0, p2a1, p2a2, p2a3, vb[2*nt], vb[2*nt+1]);
            }
        }
        __syncthreads();
    }

    // publish final l
    if (tg == 0) {
        if (sh == 0) { sL1[sr0] = lRun0; sL1[sr1] = lRun1; }
        else         { sL2[sr0] = lRun0; sL2[sr1] = lRun1; }
    }
    __syncthreads();

    // ---- epilogue (PV layout) ----
    float lam = g_lam[p];
    int r_0 = pm0 + g, r_1 = pm0 + g + 8;
    float l1_0 = sL1[r_0], l1_1 = sL1[r_1];
    float l2_0 = sL2[r_0], l2_1 = sL2[r_1];
    float al0 = alpha_map[(size_t)b*NQ + qb + r_0];
    float al1 = alpha_map[(size_t)b*NQ + qb + r_1];
    float w1_0 = (1.f + al0) / l1_0, w2_0 = -al0 * lam / l2_0, i2_0 = 1.f / l2_0;
    float w1_1 = (1.f + al1) / l1_1, w2_1 = -al1 * lam / l2_1, i2_1 = 1.f / l2_1;

    float* o0 = g_xo + ((size_t)(b*NQ + qb + r_0))*DIMC;
    float* o1 = g_xo + ((size_t)(b*NQ + qb + r_1))*DIMC;
#pragma unroll
    for (int nt = 0; nt < 4; nt++) {
        int col = pn0 + 8*nt + 2*tg;
        float2 t;
        t.x = w1_0*pacc[0][nt][0] + w2_0*pacc[1][nt][0];
        t.y = w1_0*pacc[0][nt][1] + w2_0*pacc[1][nt][1];
        *(float2*)(o0 + h1*HD + col) = t;
        t.x = w1_1*pacc[0][nt][2] + w2_1*pacc[1][nt][2];
        t.y = w1_1*pacc[0][nt][3] + w2_1*pacc[1][nt][3];
        *(float2*)(o1 + h1*HD + col) = t;
        t.x = i2_0*pacc[2][nt][0];
        t.y = i2_0*pacc[2][nt][1];
        *(float2*)(o0 + h2*HD + col) = t;
        t.x = i2_1*pacc[2][nt][2];
        t.y = i2_1*pacc[2][nt][3];
        *(float2*)(o1 + h2*HD + col) = t;
    }
}

// ---------------- launch ---------------------------------------------------
#define ATT_SMEM (12*TW*4 + 4*64*4)

extern "C" void kernel_launch(void* const* d_in, const int* in_sizes, int n_in,
                              void* d_out, int out_size)
{
    const float* x_q      = (const float*)d_in[0];
    const float* x_kv     = (const float*)d_in[1];
    const int*   coords_q = (const int*)  d_in[2];
    const int*   coords_k = (const int*)  d_in[3];
    const float* alpha    = (const float*)d_in[4];
    const float* Wq       = (const float*)d_in[5];
    const float* bq       = (const float*)d_in[6];
    const float* Wk       = (const float*)d_in[7];
    const float* bk       = (const float*)d_in[8];
    const float* Wv       = (const float*)d_in[9];
    const float* bv       = (const float*)d_in[10];
    const float* lq1      = (const float*)d_in[11];
    const float* lk1      = (const float*)d_in[12];
    const float* lq2      = (const float*)d_in[13];
    const float* lk2      = (const float*)d_in[14];
    const float* rpe      = (const float*)d_in[15];
    const float* Wp       = (const float*)d_in[16];
    const float* bp       = (const float*)d_in[17];
    float* out = (float*)d_out;

    cudaFuncSetAttribute(attn_kernel,
                         cudaFuncAttributeMaxDynamicSharedMemorySize, ATT_SMEM);

    lam_kernel<<<1, 32>>>(lq1, lk1, lq2, lk2);
    rpk_kernel<<<(TABLE*4 + 255)/256, 256>>>(rpe);

    qkv_kernel<<<dim3(32, 8, 3), 256>>>(x_q, x_kv, Wq, bq, Wk, bk, Wv, bv);

    attn_kernel<<<dim3(16, 4, 4), 256, ATT_SMEM>>>(coords_q, coords_k, alpha);

    proj_kernel<<<dim3(32, 8), 256>>>(Wp, bp, out);
}

// round 17
// speedup vs baseline: 1.2278x; 1.2278x over previous
#include <cuda_runtime.h>
#include <cuda_fp16.h>

#define DIMC 512
#define NH   8
#define HD   64
#define BATCH 4
#define NQ   1024
#define NKV  1024
#define TABLE 66049   // 257*257
#define LOG2E 1.44269504f

// ---------------- scratch (device globals: no allocation allowed) ----------
__device__ unsigned g_q [BATCH*NH*NQ *32];   // fp16 half2 [B][H][N][32]; Q pre-scaled by 0.125*log2e
__device__ unsigned g_k [BATCH*NH*NKV*32];
__device__ unsigned g_v [BATCH*NH*NKV*32];
__device__ float    g_xo[BATCH*NQ*DIMC];
__device__ float    g_lam[NH/2];
__device__ unsigned g_rpk[TABLE*4];          // half2(rpe[idx][p], rpe[idx][p+4]) * log2e

// ---------------- lambda ---------------------------------------------------
__global__ void lam_kernel(const float* __restrict__ lq1, const float* __restrict__ lk1,
                           const float* __restrict__ lq2, const float* __restrict__ lk2)
{
    int p = threadIdx.x;
    if (p < NH/2) {
        float a = 0.f, c = 0.f;
        for (int d = 0; d < HD; d++) {
            a += lq1[p*HD+d] * lk1[p*HD+d];
            c += lq2[p*HD+d] * lk2[p*HD+d];
        }
        g_lam[p] = __expf(a) - __expf(c) + 0.8f;
    }
}

// ---------------- RPE repack: half2(h, h+4)*log2e per (idx, pair) ----------
__global__ void rpk_kernel(const float* __restrict__ rpe)
{
    int i = blockIdx.x*256 + threadIdx.x;
    if (i < TABLE*4) {
        int idx = i >> 2, p = i & 3;
        __half2 h = __floats2half2_rn(rpe[idx*8 + p]*LOG2E, rpe[idx*8 + p + 4]*LOG2E);
        g_rpk[i] = *(unsigned*)&h;
    }
}

// ---------------- helpers ---------------------------------------------------
__device__ __forceinline__ void mma_f16(float c[4],
    unsigned a0, unsigned a1, unsigned a2, unsigned a3,
    unsigned b0, unsigned b1)
{
    asm volatile(
        "mma.sync.aligned.m16n8k16.row.col.f32.f16.f16.f32 "
        "{%0,%1,%2,%3},{%4,%5,%6,%7},{%8,%9},{%0,%1,%2,%3};\n"
        : "+f"(c[0]), "+f"(c[1]), "+f"(c[2]), "+f"(c[3])
        : "r"(a0), "r"(a1), "r"(a2), "r"(a3), "r"(b0), "r"(b1));
}

__device__ __forceinline__ void ldsm_x4(
    unsigned& r0, unsigned& r1, unsigned& r2, unsigned& r3, unsigned saddr)
{
    asm volatile(
        "ldmatrix.sync.aligned.m8n8.x4.shared.b16 {%0,%1,%2,%3}, [%4];"
        : "=r"(r0), "=r"(r1), "=r"(r2), "=r"(r3) : "r"(saddr));
}

__device__ __forceinline__ void ldsm_x4_trans(
    unsigned& r0, unsigned& r1, unsigned& r2, unsigned& r3, unsigned saddr)
{
    asm volatile(
        "ldmatrix.sync.aligned.m8n8.x4.trans.shared.b16 {%0,%1,%2,%3}, [%4];"
        : "=r"(r0), "=r"(r1), "=r"(r2), "=r"(r3) : "r"(saddr));
}

__device__ __forceinline__ unsigned pack_h2(float lo, float hi) {
    __half2 h = __floats2half2_rn(lo, hi);
    return *(unsigned*)&h;
}
__device__ __forceinline__ unsigned h2u(__half2 h) { return *(unsigned*)&h; }
__device__ __forceinline__ float ex2(float x) {
    float r; asm("ex2.approx.f32 %0, %1;" : "=f"(r) : "f"(x)); return r;
}

// ---------------- fp16 GEMM (R14 winner + output-scale param) --------------
#define GST 20

__device__ __forceinline__ void gemm_body(
    const float* __restrict__ A, const float* __restrict__ W,
    const float* __restrict__ bias, void* __restrict__ C,
    int mode, int bm, int bn, float osc)
{
    __shared__ unsigned As[2][128][GST];
    __shared__ unsigned Ws[2][64][GST];

    int tid  = threadIdx.x;
    int wid  = tid >> 5;
    int lane = tid & 31;
    int g    = lane >> 2;
    int tg   = lane & 3;
    int wm   = (wid >> 1) * 32;
    int wn   = (wid & 1) * 32;

    float acc[2][4][4];
#pragma unroll
    for (int mf = 0; mf < 2; mf++)
#pragma unroll
        for (int nf = 0; nf < 4; nf++)
#pragma unroll
            for (int e = 0; e < 4; e++) acc[mf][nf][e] = 0.f;

    int rA = tid >> 1, hA = tid & 1;
    const float* Arow = A + (size_t)(bm + rA) * DIMC + hA * 16;
    int rW = tid >> 2, qW = tid & 3;
    const float* Wrow = W + (size_t)(bn + rW) * DIMC + qW * 8;

    float4 av[4], wv[2];
#pragma unroll
    for (int i = 0; i < 4; i++) av[i] = *(const float4*)(Arow + 4*i);
    wv[0] = *(const float4*)(Wrow);
    wv[1] = *(const float4*)(Wrow + 4);

#pragma unroll
    for (int i = 0; i < 4; i++) {
        As[0][rA][hA*8 + 2*i]   = pack_h2(av[i].x, av[i].y);
        As[0][rA][hA*8 + 2*i+1] = pack_h2(av[i].z, av[i].w);
    }
    Ws[0][rW][qW*4+0] = pack_h2(wv[0].x, wv[0].y);
    Ws[0][rW][qW*4+1] = pack_h2(wv[0].z, wv[0].w);
    Ws[0][rW][qW*4+2] = pack_h2(wv[1].x, wv[1].y);
    Ws[0][rW][qW*4+3] = pack_h2(wv[1].z, wv[1].w);
    __syncthreads();

    for (int k0 = 0; k0 < DIMC; k0 += 32) {
        int  buf  = (k0 >> 5) & 1;
        bool more = (k0 + 32 < DIMC);
        if (more) {
#pragma unroll
            for (int i = 0; i < 4; i++)
                av[i] = *(const float4*)(Arow + k0 + 32 + 4*i);
            wv[0] = *(const float4*)(Wrow + k0 + 32);
            wv[1] = *(const float4*)(Wrow + k0 + 36);
        }

#pragma unroll
        for (int s = 0; s < 2; s++) {
            int kw = s * 8;
            unsigned af[2][4], bf[4][2];
#pragma unroll
            for (int mf = 0; mf < 2; mf++) {
                int m0 = wm + mf*16 + g;
                af[mf][0] = As[buf][m0  ][kw+tg];
                af[mf][1] = As[buf][m0+8][kw+tg];
                af[mf][2] = As[buf][m0  ][kw+4+tg];
                af[mf][3] = As[buf][m0+8][kw+4+tg];
            }
#pragma unroll
            for (int nf = 0; nf < 4; nf++) {
                int n0 = wn + nf*8 + g;
                bf[nf][0] = Ws[buf][n0][kw+tg];
                bf[nf][1] = Ws[buf][n0][kw+4+tg];
            }
#pragma unroll
            for (int mf = 0; mf < 2; mf++)
#pragma unroll
                for (int nf = 0; nf < 4; nf++)
                    mma_f16(acc[mf][nf], af[mf][0], af[mf][1], af[mf][2], af[mf][3],
                            bf[nf][0], bf[nf][1]);
        }

        if (more) {
            int nb = buf ^ 1;
#pragma unroll
            for (int i = 0; i < 4; i++) {
                As[nb][rA][hA*8 + 2*i]   = pack_h2(av[i].x, av[i].y);
                As[nb][rA][hA*8 + 2*i+1] = pack_h2(av[i].z, av[i].w);
            }
            Ws[nb][rW][qW*4+0] = pack_h2(wv[0].x, wv[0].y);
            Ws[nb][rW][qW*4+1] = pack_h2(wv[0].z, wv[0].w);
            Ws[nb][rW][qW*4+2] = pack_h2(wv[1].x, wv[1].y);
            Ws[nb][rW][qW*4+3] = pack_h2(wv[1].z, wv[1].w);
            __syncthreads();
        }
    }

#pragma unroll
    for (int nf = 0; nf < 4; nf++) {
        int c0 = bn + wn + nf*8 + 2*tg;
        float b0 = bias[c0], b1 = bias[c0+1];
#pragma unroll
        for (int mf = 0; mf < 2; mf++) {
            int r0 = bm + wm + mf*16 + g;
            float2 o0 = {acc[mf][nf][0] + b0, acc[mf][nf][1] + b1};
            float2 o1 = {acc[mf][nf][2] + b0, acc[mf][nf][3] + b1};
            if (mode == 0) {
                *(float2*)((float*)C + (size_t)r0*DIMC + c0)     = o0;
                *(float2*)((float*)C + (size_t)(r0+8)*DIMC + c0) = o1;
            } else {
                unsigned w0 = pack_h2(o0.x*osc, o0.y*osc);
                unsigned w1 = pack_h2(o1.x*osc, o1.y*osc);
                int h = c0 >> 6, hp = (c0 & 63) >> 1;
                int b_  = r0 >> 10, nq = r0 & 1023;
                ((unsigned*)C)[((size_t)(b_*NH + h)*NQ + nq)*32 + hp] = w0;
                b_ = (r0+8) >> 10; nq = (r0+8) & 1023;
                ((unsigned*)C)[((size_t)(b_*NH + h)*NQ + nq)*32 + hp] = w1;
            }
        }
    }
}

__global__ __launch_bounds__(256) void qkv_kernel(
    const float* __restrict__ x_q, const float* __restrict__ x_kv,
    const float* __restrict__ Wq, const float* __restrict__ bq,
    const float* __restrict__ Wk, const float* __restrict__ bk,
    const float* __restrict__ Wv, const float* __restrict__ bv)
{
    int z = blockIdx.z;
    const float* A    = (z == 0) ? x_q : x_kv;
    const float* W    = (z == 0) ? Wq : (z == 1) ? Wk : Wv;
    const float* bias = (z == 0) ? bq : (z == 1) ? bk : bv;
    void* C           = (z == 0) ? (void*)g_q : (z == 1) ? (void*)g_k : (void*)g_v;
    float osc         = (z == 0) ? 0.125f*LOG2E : 1.f;
    gemm_body(A, W, bias, C, 1, blockIdx.x*128, blockIdx.y*64, osc);
}

__global__ __launch_bounds__(256) void proj_kernel(
    const float* __restrict__ Wp, const float* __restrict__ bp, float* __restrict__ out)
{
    gemm_body(g_xo, Wp, bp, out, 0, blockIdx.x*128, blockIdx.y*64, 1.f);
}

// ---------------- fp16 tensor-core differential flash attention -------------
// EXACT R15 structure (best: 215.8us) with two zero-smem-cost changes:
//  - same-tile RPE gather moved BEFORE the score mma (L2 latency hides under
//    the mma); single sB buffer, same barriers, same smem
//  - log2-domain softmax: Q pre-scaled, table pre-multiplied by log2e,
//    bare ex2, scale+bias FMA -> FADD
#define ST 36
#define TW (64*ST)

__global__ __launch_bounds__(256, 2) void attn_kernel(
    const int* __restrict__ coords_q, const int* __restrict__ coords_k,
    const float* __restrict__ alpha_map)
{
    extern __shared__ __align__(16) unsigned su[];
    unsigned* sQ1 = su;            // [64][36] half2 words
    unsigned* sQ2 = sQ1 + TW;
    unsigned* sK1 = sQ2 + TW;
    unsigned* sK2 = sK1 + TW;
    unsigned* sV1 = sK2 + TW;
    unsigned* sV2 = sV1 + TW;
    unsigned* sS1 = sV2 + TW;      // P tiles (fp16 pairs)
    unsigned* sS2 = sS1 + TW;
    unsigned* sB1 = sS2 + TW;      // bias tiles (fp16 pairs, log2e units)
    unsigned* sB2 = sB1 + TW;
    float* sC1 = (float*)(sB2 + TW);   // [64] corrections
    float* sC2 = sC1 + 64;
    float* sL1 = sC2 + 64;             // [64] final l
    float* sL2 = sL1 + 64;
    int*   sCk = (int*)(sL2 + 64);     // [128]

    int tid  = threadIdx.x;
    int w    = tid >> 5;
    int lane = tid & 31;
    int g    = lane >> 2;
    int tg   = lane & 3;

    int qb = blockIdx.x * 64;
    int p  = blockIdx.y;
    int b  = blockIdx.z;
    int h1 = p, h2 = p + 4;

    int sh  = w >> 2;          // score head
    int sm0 = (w & 3) * 16;    // score m-strip
    int pm0 = (w >> 1) * 16;   // PV m-strip
    int pn0 = (w & 1) * 32;    // PV n-half

    const unsigned* q1g = g_q + ((size_t)(b*NH+h1)*NQ + qb)*32;
    const unsigned* q2g = g_q + ((size_t)(b*NH+h2)*NQ + qb)*32;
    const unsigned* k1base = g_k + ((size_t)(b*NH+h1)*NKV)*32;
    const unsigned* k2base = g_k + ((size_t)(b*NH+h2)*NKV)*32;
    const unsigned* v1base = g_v + ((size_t)(b*NH+h1)*NKV)*32;
    const unsigned* v2base = g_v + ((size_t)(b*NH+h2)*NKV)*32;

    // ---- stage Q ----
    for (int c = tid; c < 512; c += 256) {
        int row = c >> 3, seg = (c & 7) * 4;
        *(uint4*)&sQ1[row*ST+seg] = *(const uint4*)(q1g + row*32 + seg);
        *(uint4*)&sQ2[row*ST+seg] = *(const uint4*)(q2g + row*32 + seg);
    }

    int sr0 = sm0 + g, sr1 = sm0 + g + 8;
    int cqx0 = 0, cqy0 = 0, cqx1 = 0, cqy1 = 0;
    if (sh == 0) {
        cqx0 = coords_q[((size_t)b*NQ + qb + sr0)*2];
        cqy0 = coords_q[((size_t)b*NQ + qb + sr0)*2 + 1];
        cqx1 = coords_q[((size_t)b*NQ + qb + sr1)*2];
        cqy1 = coords_q[((size_t)b*NQ + qb + sr1)*2 + 1];
    }

    // ---- ldmatrix per-lane byte offsets ----
    int aRow = (lane & 7) + ((lane >> 3) & 1) * 8;
    unsigned aOff = (unsigned)((aRow*ST + (lane >> 4)*4) * 4);
    int kRow = ((lane >> 4) * 8) + (lane & 7);
    unsigned kOff = (unsigned)((kRow*ST + ((lane >> 3) & 1)*4) * 4);
    int lt = lane >> 3, lr = lane & 7;
    unsigned lmOff0 = ((((lt & 1) * 8 + lr) * ST) + (pn0 >> 1) + ((lt >> 1) * 4)) * 4;
    unsigned lmOff1 = lmOff0 + 32;

    unsigned sV1a = (unsigned)__cvta_generic_to_shared(sV1);
    unsigned sV2a = (unsigned)__cvta_generic_to_shared(sV2);
    unsigned sS1a = (unsigned)__cvta_generic_to_shared(sS1);
    unsigned sS2a = (unsigned)__cvta_generic_to_shared(sS2);

    float mOld0 = -1e30f, mOld1 = -1e30f, lRun0 = 0.f, lRun1 = 0.f;

    float pacc[3][4][4];
#pragma unroll
    for (int pr = 0; pr < 3; pr++)
#pragma unroll
        for (int nt = 0; nt < 4; nt++)
#pragma unroll
            for (int e = 0; e < 4; e++) pacc[pr][nt][e] = 0.f;

    const unsigned* Qs = sh ? sQ2 : sQ1;
    const unsigned* Ks = sh ? sK2 : sK1;
    unsigned* Ss       = sh ? sS2 : sS1;
    unsigned* Bs       = sh ? sB2 : sB1;
    float* sCa         = sh ? sC2 : sC1;

    unsigned qFrag = (unsigned)__cvta_generic_to_shared(Qs) + (unsigned)(sm0*ST*4) + aOff;
    unsigned kFrag = (unsigned)__cvta_generic_to_shared(Ks) + kOff;
    unsigned p1Frag = sS1a + (unsigned)(pm0*ST*4) + aOff;
    unsigned p2Frag = sS2a + (unsigned)(pm0*ST*4) + aOff;

    for (int kb = 0; kb < NKV; kb += 64) {
        // ---- stage K/V + coords ----
        for (int c = tid; c < 512; c += 256) {
            int row = c >> 3, seg = (c & 7) * 4;
            int go = (kb + row)*32 + seg;
            *(uint4*)&sK1[row*ST+seg] = *(const uint4*)(k1base + go);
            *(uint4*)&sK2[row*ST+seg] = *(const uint4*)(k2base + go);
            *(uint4*)&sV1[row*ST+seg] = *(const uint4*)(v1base + go);
            *(uint4*)&sV2[row*ST+seg] = *(const uint4*)(v2base + go);
        }
        if (tid < 128) sCk[tid] = coords_k[((size_t)b*NKV + kb)*2 + tid];
        __syncthreads();

        // ---- sh=0 warps: issue packed RPE gathers FIRST (latency hides
        //      under the score mma below; stores land before the barrier) ----
        if (sh == 0) {
#pragma unroll
            for (int nt = 0; nt < 8; nt++) {
                int c0 = 8*nt + 2*tg, c1 = c0 + 1;
                int kx0 = sCk[c0*2], ky0 = sCk[c0*2+1];
                int kx1 = sCk[c1*2], ky1 = sCk[c1*2+1];

                int r0 = min(max(cqx0 - kx0 + 128, 0), 256);
                int r1 = min(max(cqy0 - ky0 + 128, 0), 256);
                unsigned w00 = __ldg(&g_rpk[(r0*257 + r1)*4 + p]);
                r0 = min(max(cqx0 - kx1 + 128, 0), 256);
                r1 = min(max(cqy0 - ky1 + 128, 0), 256);
                unsigned w01 = __ldg(&g_rpk[(r0*257 + r1)*4 + p]);
                __half2 a = *(__half2*)&w00, bb = *(__half2*)&w01;
                sB1[sr0*ST + 4*nt + tg] = h2u(__halves2half2(__low2half(a),  __low2half(bb)));
                sB2[sr0*ST + 4*nt + tg] = h2u(__halves2half2(__high2half(a), __high2half(bb)));

                r0 = min(max(cqx1 - kx0 + 128, 0), 256);
                r1 = min(max(cqy1 - ky0 + 128, 0), 256);
                unsigned w10 = __ldg(&g_rpk[(r0*257 + r1)*4 + p]);
                r0 = min(max(cqx1 - kx1 + 128, 0), 256);
                r1 = min(max(cqy1 - ky1 + 128, 0), 256);
                unsigned w11 = __ldg(&g_rpk[(r0*257 + r1)*4 + p]);
                __half2 c = *(__half2*)&w10, d = *(__half2*)&w11;
                sB1[sr1*ST + 4*nt + tg] = h2u(__halves2half2(__low2half(c),  __low2half(d)));
                sB2[sr1*ST + 4*nt + tg] = h2u(__halves2half2(__high2half(c), __high2half(d)));
            }
        }

        // ---- scores: ldmatrix fragments + 4 k16 steps x 8 nt ----
        float sc[8][4];
#pragma unroll
        for (int nt = 0; nt < 8; nt++)
#pragma unroll
            for (int e = 0; e < 4; e++) sc[nt][e] = 0.f;

#pragma unroll
        for (int s = 0; s < 4; s++) {
            unsigned a0, a1, a2, a3;
            ldsm_x4(a0, a1, a2, a3, qFrag + s*32);
#pragma unroll
            for (int np = 0; np < 4; np++) {
                unsigned b0, b1, c0, c1;
                ldsm_x4(b0, b1, c0, c1, kFrag + (unsigned)(np*16*ST*4) + s*32);
                mma_f16(sc[2*np],   a0, a1, a2, a3, b0, b1);
                mma_f16(sc[2*np+1], a0, a1, a2, a3, c0, c1);
            }
        }
        __syncthreads();

        // ---- add bias from smem (log2 domain; Q already scaled) ----
#pragma unroll
        for (int nt = 0; nt < 8; nt++) {
            __half2 b0 = *(__half2*)&Bs[sr0*ST + 4*nt + tg];
            __half2 b1 = *(__half2*)&Bs[sr1*ST + 4*nt + tg];
            sc[nt][0] += __low2float(b0);
            sc[nt][1] += __high2float(b0);
            sc[nt][2] += __low2float(b1);
            sc[nt][3] += __high2float(b1);
        }

        // ---- online softmax (log2 domain; rows sr0, sr1; quad reduction) ---
        float rm0 = sc[0][0], rm1 = sc[0][2];
#pragma unroll
        for (int nt = 0; nt < 8; nt++) {
            rm0 = fmaxf(rm0, fmaxf(sc[nt][0], sc[nt][1]));
            rm1 = fmaxf(rm1, fmaxf(sc[nt][2], sc[nt][3]));
        }
#pragma unroll
        for (int o = 1; o < 4; o <<= 1) {
            rm0 = fmaxf(rm0, __shfl_xor_sync(0xffffffffu, rm0, o));
            rm1 = fmaxf(rm1, __shfl_xor_sync(0xffffffffu, rm1, o));
        }
        float nm0 = fmaxf(mOld0, rm0), nm1 = fmaxf(mOld1, rm1);
        float corr0 = ex2(mOld0 - nm0), corr1 = ex2(mOld1 - nm1);

        float sum0 = 0.f, sum1 = 0.f;
#pragma unroll
        for (int nt = 0; nt < 8; nt++) {
            float e00 = ex2(sc[nt][0] - nm0);
            float e01 = ex2(sc[nt][1] - nm0);
            float e10 = ex2(sc[nt][2] - nm1);
            float e11 = ex2(sc[nt][3] - nm1);
            sum0 += e00 + e01;
            sum1 += e10 + e11;
            Ss[sr0*ST + 4*nt + tg] = pack_h2(e00, e01);
            Ss[sr1*ST + 4*nt + tg] = pack_h2(e10, e11);
        }
#pragma unroll
        for (int o = 1; o < 4; o <<= 1) {
            sum0 += __shfl_xor_sync(0xffffffffu, sum0, o);
            sum1 += __shfl_xor_sync(0xffffffffu, sum1, o);
        }
        lRun0 = lRun0*corr0 + sum0;
        lRun1 = lRun1*corr1 + sum1;
        mOld0 = nm0; mOld1 = nm1;
        if (tg == 0) { sCa[sr0] = corr0; sCa[sr1] = corr1; }
        __syncthreads();

        // ---- PV: rescale accumulators, then fp16 mma (ldmatrix P and V^T) --
        float c1r0 = sC1[pm0+g], c1r1 = sC1[pm0+g+8];
        float c2r0 = sC2[pm0+g], c2r1 = sC2[pm0+g+8];
#pragma unroll
        for (int nt = 0; nt < 4; nt++) {
            pacc[0][nt][0] *= c1r0; pacc[0][nt][1] *= c1r0;
            pacc[0][nt][2] *= c1r1; pacc[0][nt][3] *= c1r1;
            pacc[1][nt][0] *= c2r0; pacc[1][nt][1] *= c2r0;
            pacc[1][nt][2] *= c2r1; pacc[1][nt][3] *= c2r1;
            pacc[2][nt][0] *= c2r0; pacc[2][nt][1] *= c2r0;
            pacc[2][nt][2] *= c2r1; pacc[2][nt][3] *= c2r1;
        }

#pragma unroll
        for (int s = 0; s < 4; s++) {
            unsigned p1a0, p1a1, p1a2, p1a3, p2a0, p2a1, p2a2, p2a3;
            ldsm_x4(p1a0, p1a1, p1a2, p1a3, p1Frag + s*32);
            ldsm_x4(p2a0, p2a1, p2a2, p2a3, p2Frag + s*32);

            unsigned rowB = (unsigned)(s * 16 * ST * 4);
            unsigned va[8], vb[8];
            ldsm_x4_trans(va[0], va[1], va[2], va[3], sV1a + rowB + lmOff0);
            ldsm_x4_trans(va[4], va[5], va[6], va[7], sV1a + rowB + lmOff1);
            ldsm_x4_trans(vb[0], vb[1], vb[2], vb[3], sV2a + rowB + lmOff0);
            ldsm_x4_trans(vb[4], vb[5], vb[6], vb[7], sV2a + rowB + lmOff1);

#pragma unroll
            for (int nt = 0; nt < 4; nt++) {
                mma_f16(pacc[0][nt], p1a0, p1a1, p1a2, p1a3, va[2*nt], va[2*nt+1]);
                mma_f16(pacc[1][nt], p2a0, p2a1, p2a2, p2a3, va[2*nt], va[2*nt+1]);
                mma_f16(pacc[2][nt], p2a0, p2a1, p2a2, p2a3, vb[2*nt], vb[2*nt+1]);
            }
        }
        __syncthreads();
    }

    // publish final l
    if (tg == 0) {
        if (sh == 0) { sL1[sr0] = lRun0; sL1[sr1] = lRun1; }
        else         { sL2[sr0] = lRun0; sL2[sr1] = lRun1; }
    }
    __syncthreads();

    // ---- epilogue (PV layout) ----
    float lam = g_lam[p];
    int r_0 = pm0 + g, r_1 = pm0 + g + 8;
    float l1_0 = sL1[r_0], l1_1 = sL1[r_1];
    float l2_0 = sL2[r_0], l2_1 = sL2[r_1];
    float al0 = alpha_map[(size_t)b*NQ + qb + r_0];
    float al1 = alpha_map[(size_t)b*NQ + qb + r_1];
    float w1_0 = (1.f + al0) / l1_0, w2_0 = -al0 * lam / l2_0, i2_0 = 1.f / l2_0;
    float w1_1 = (1.f + al1) / l1_1, w2_1 = -al1 * lam / l2_1, i2_1 = 1.f / l2_1;

    float* o0 = g_xo + ((size_t)(b*NQ + qb + r_0))*DIMC;
    float* o1 = g_xo + ((size_t)(b*NQ + qb + r_1))*DIMC;
#pragma unroll
    for (int nt = 0; nt < 4; nt++) {
        int col = pn0 + 8*nt + 2*tg;
        float2 t;
        t.x = w1_0*pacc[0][nt][0] + w2_0*pacc[1][nt][0];
        t.y = w1_0*pacc[0][nt][1] + w2_0*pacc[1][nt][1];
        *(float2*)(o0 + h1*HD + col) = t;
        t.x = w1_1*pacc[0][nt][2] + w2_1*pacc[1][nt][2];
        t.y = w1_1*pacc[0][nt][3] + w2_1*pacc[1][nt][3];
        *(float2*)(o1 + h1*HD + col) = t;
        t.x = i2_0*pacc[2][nt][0];
        t.y = i2_0*pacc[2][nt][1];
        *(float2*)(o0 + h2*HD + col) = t;
        t.x = i2_1*pacc[2][nt][2];
        t.y = i2_1*pacc[2][nt][3];
        *(float2*)(o1 + h2*HD + col) = t;
    }
}

// ---------------- launch ---------------------------------------------------
#define ATT_SMEM (10*TW*4 + 4*64*4 + 128*4)

extern "C" void kernel_launch(void* const* d_in, const int* in_sizes, int n_in,
                              void* d_out, int out_size)
{
    const float* x_q      = (const float*)d_in[0];
    const float* x_kv     = (const float*)d_in[1];
    const int*   coords_q = (const int*)  d_in[2];
    const int*   coords_k = (const int*)  d_in[3];
    const float* alpha    = (const float*)d_in[4];
    const float* Wq       = (const float*)d_in[5];
    const float* bq       = (const float*)d_in[6];
    const float* Wk       = (const float*)d_in[7];
    const float* bk       = (const float*)d_in[8];
    const float* Wv       = (const float*)d_in[9];
    const float* bv       = (const float*)d_in[10];
    const float* lq1      = (const float*)d_in[11];
    const float* lk1      = (const float*)d_in[12];
    const float* lq2      = (const float*)d_in[13];
    const float* lk2      = (const float*)d_in[14];
    const float* rpe      = (const float*)d_in[15];
    const float* Wp       = (const float*)d_in[16];
    const float* bp       = (const float*)d_in[17];
    float* out = (float*)d_out;

    cudaFuncSetAttribute(attn_kernel,
                         cudaFuncAttributeMaxDynamicSharedMemorySize, ATT_SMEM);

    lam_kernel<<<1, 32>>>(lq1, lk1, lq2, lk2);
    rpk_kernel<<<(TABLE*4 + 255)/256, 256>>>(rpe);

    qkv_kernel<<<dim3(32, 8, 3), 256>>>(x_q, x_kv, Wq, bq, Wk, bk, Wv, bv);

    attn_kernel<<<dim3(16, 4, 4), 256, ATT_SMEM>>>(coords_q, coords_k, alpha);

    proj_kernel<<<dim3(32, 8), 256>>>(Wp, bp, out);
}